// round 1
// baseline (speedup 1.0000x reference)
#include <cuda_runtime.h>
#include <math.h>

#define Bn   4
#define Tn   2048
#define En   1024
#define Hn   16
#define HDn  64
#define Mn   (Bn * Tn)          // 8192 rows
#define QKVN (3 * En)           // 3072

// Scratch (no cudaMalloc allowed)
__device__ float g_qkv[Mn * QKVN];   // [8192][3072] : q|k|v per row
__device__ float g_ctx[Mn * En];     // [8192][1024] : attention context

// ---------------------------------------------------------------------------
// SGEMM: C[M,N] = A[M,K] @ W[N,K]^T + bias[N]
// 128x128 block tile, BK=8, 256 threads, 8x8 per-thread micro-tile.
// ---------------------------------------------------------------------------
__global__ __launch_bounds__(256, 2)
void sgemm_tn(const float* __restrict__ A, const float* __restrict__ W,
              const float* __restrict__ bias, float* __restrict__ C,
              int M, int N, int K) {
    const int BM = 128, BN = 128, BK = 8;
    __shared__ float As[BK][BM];
    __shared__ float Bs[BK][BN];

    int tid = threadIdx.x;
    int tx = tid & 15;          // 0..15 -> N direction
    int ty = tid >> 4;          // 0..15 -> M direction
    int row0 = blockIdx.y * BM;
    int col0 = blockIdx.x * BN;

    int lr = tid >> 1;          // 0..127
    int lk = (tid & 1) * 4;     // 0 or 4
    const float* Ag = A + (size_t)(row0 + lr) * K + lk;
    const float* Wg = W + (size_t)(col0 + lr) * K + lk;

    float acc[8][8];
#pragma unroll
    for (int i = 0; i < 8; i++)
#pragma unroll
        for (int j = 0; j < 8; j++) acc[i][j] = 0.0f;

    for (int k0 = 0; k0 < K; k0 += BK) {
        float4 av = *(const float4*)(Ag + k0);
        float4 wv = *(const float4*)(Wg + k0);
        As[lk + 0][lr] = av.x; As[lk + 1][lr] = av.y;
        As[lk + 2][lr] = av.z; As[lk + 3][lr] = av.w;
        Bs[lk + 0][lr] = wv.x; Bs[lk + 1][lr] = wv.y;
        Bs[lk + 2][lr] = wv.z; Bs[lk + 3][lr] = wv.w;
        __syncthreads();
#pragma unroll
        for (int kk = 0; kk < BK; kk++) {
            float a[8], b[8];
            *(float4*)&a[0] = *(const float4*)&As[kk][ty * 8];
            *(float4*)&a[4] = *(const float4*)&As[kk][ty * 8 + 4];
            *(float4*)&b[0] = *(const float4*)&Bs[kk][tx * 8];
            *(float4*)&b[4] = *(const float4*)&Bs[kk][tx * 8 + 4];
#pragma unroll
            for (int i = 0; i < 8; i++)
#pragma unroll
                for (int j = 0; j < 8; j++) acc[i][j] += a[i] * b[j];
        }
        __syncthreads();
    }

    float bv[8];
#pragma unroll
    for (int j = 0; j < 8; j++) bv[j] = bias[col0 + tx * 8 + j];
#pragma unroll
    for (int i = 0; i < 8; i++) {
        float* Cp = C + (size_t)(row0 + ty * 8 + i) * N + col0 + tx * 8;
#pragma unroll
        for (int j = 0; j < 8; j++) Cp[j] = acc[i][j] + bv[j];
    }
}

// ---------------------------------------------------------------------------
// Flash attention (fp32). One block = one (b,h) x 64-row Q tile.
// Iterates over KV in 64-row tiles with online softmax.
// smem: Qs[d][i], Ks[d][j] transposed (pad 68); Vs[j][d] (pad 68); Ps[j][i] (pad 65)
// ---------------------------------------------------------------------------
#define PADQ 68
#define PADP 65
#define ATTN_SMEM_FLOATS (64 * PADQ * 3 + 64 * PADP)
#define ATTN_SMEM_BYTES  (ATTN_SMEM_FLOATS * 4)

extern __shared__ float sm_attn[];

__global__ __launch_bounds__(256)
void attn_kernel(const float* __restrict__ qkv,
                 const unsigned char* __restrict__ mask,
                 float* __restrict__ ctx) {
    float* Qs = sm_attn;                 // [64][PADQ]  Qs[d*PADQ + i]
    float* Ks = Qs + 64 * PADQ;          // [64][PADQ]  Ks[d*PADQ + j]
    float* Vs = Ks + 64 * PADQ;          // [64][PADQ]  Vs[j*PADQ + d]
    float* Ps = Vs + 64 * PADQ;          // [64][PADP]  Ps[j*PADP + i]

    int tid = threadIdx.x;
    int tx = tid & 15;       // kv / head-dim direction (4 elems)
    int ty = tid >> 4;       // q-row direction (4 elems)
    int b  = blockIdx.y >> 4;
    int h  = blockIdx.y & 15;
    int q0 = blockIdx.x * 64;

    const float* base = qkv + (size_t)b * Tn * QKVN + h * HDn;  // q cols
    const float  scale = 0.125f;  // 1/sqrt(64)

    // Load Q tile transposed: Qs[d][i]
#pragma unroll
    for (int it = 0; it < 4; it++) {
        int idx = tid + it * 256;         // 0..1023 float4s
        int r = idx >> 4;                 // q row in tile
        int d4 = (idx & 15) * 4;
        float4 v = *(const float4*)(base + (size_t)(q0 + r) * QKVN + d4);
        Qs[(d4 + 0) * PADQ + r] = v.x;
        Qs[(d4 + 1) * PADQ + r] = v.y;
        Qs[(d4 + 2) * PADQ + r] = v.z;
        Qs[(d4 + 3) * PADQ + r] = v.w;
    }

    float m_prev[4], lsum[4], o[4][4];
#pragma unroll
    for (int r = 0; r < 4; r++) {
        m_prev[r] = -1e30f; lsum[r] = 0.0f;
#pragma unroll
        for (int c = 0; c < 4; c++) o[r][c] = 0.0f;
    }

    const float* kbase = base + En;       // k cols
    const float* vbase = base + 2 * En;   // v cols

    for (int kv0 = 0; kv0 < Tn; kv0 += 64) {
        // Load K (transposed) and V (natural)
#pragma unroll
        for (int it = 0; it < 4; it++) {
            int idx = tid + it * 256;
            int r = idx >> 4;
            int d4 = (idx & 15) * 4;
            float4 kv = *(const float4*)(kbase + (size_t)(kv0 + r) * QKVN + d4);
            Ks[(d4 + 0) * PADQ + r] = kv.x;
            Ks[(d4 + 1) * PADQ + r] = kv.y;
            Ks[(d4 + 2) * PADQ + r] = kv.z;
            Ks[(d4 + 3) * PADQ + r] = kv.w;
            float4 vv = *(const float4*)(vbase + (size_t)(kv0 + r) * QKVN + d4);
            *(float4*)&Vs[r * PADQ + d4] = vv;
        }
        __syncthreads();

        // S = Q K^T  (4x4 per thread)
        float s[4][4];
#pragma unroll
        for (int r = 0; r < 4; r++)
#pragma unroll
            for (int c = 0; c < 4; c++) s[r][c] = 0.0f;
#pragma unroll 16
        for (int d = 0; d < 64; d++) {
            float4 a = *(const float4*)&Qs[d * PADQ + ty * 4];
            float4 kk = *(const float4*)&Ks[d * PADQ + tx * 4];
            float ar[4] = {a.x, a.y, a.z, a.w};
            float kr[4] = {kk.x, kk.y, kk.z, kk.w};
#pragma unroll
            for (int r = 0; r < 4; r++)
#pragma unroll
                for (int c = 0; c < 4; c++) s[r][c] += ar[r] * kr[c];
        }

        // scale + mask
        int kvb = kv0 + tx * 4;
#pragma unroll
        for (int c = 0; c < 4; c++) {
            bool mk = mask[b * Tn + kvb + c] != 0;
#pragma unroll
            for (int r = 0; r < 4; r++)
                s[r][c] = mk ? -1e30f : s[r][c] * scale;
        }

        // online softmax
        float newm[4], alpha[4], rs[4];
#pragma unroll
        for (int r = 0; r < 4; r++) {
            float mx = fmaxf(fmaxf(s[r][0], s[r][1]), fmaxf(s[r][2], s[r][3]));
#pragma unroll
            for (int off = 8; off > 0; off >>= 1)
                mx = fmaxf(mx, __shfl_xor_sync(0xffffffffu, mx, off));
            newm[r] = fmaxf(m_prev[r], mx);
            alpha[r] = __expf(m_prev[r] - newm[r]);
            float srow = 0.0f;
#pragma unroll
            for (int c = 0; c < 4; c++) {
                float p = __expf(s[r][c] - newm[r]);
                s[r][c] = p;
                srow += p;
            }
#pragma unroll
            for (int off = 8; off > 0; off >>= 1)
                srow += __shfl_xor_sync(0xffffffffu, srow, off);
            rs[r] = srow;
        }
#pragma unroll
        for (int r = 0; r < 4; r++) {
            lsum[r] = lsum[r] * alpha[r] + rs[r];
            m_prev[r] = newm[r];
#pragma unroll
            for (int c = 0; c < 4; c++) o[r][c] *= alpha[r];
        }

        // Ps[j][i] = P^T
#pragma unroll
        for (int c = 0; c < 4; c++)
#pragma unroll
            for (int r = 0; r < 4; r++)
                Ps[(tx * 4 + c) * PADP + ty * 4 + r] = s[r][c];
        __syncthreads();

        // O += P V
#pragma unroll 8
        for (int j = 0; j < 64; j++) {
            float pa[4];
#pragma unroll
            for (int r = 0; r < 4; r++) pa[r] = Ps[j * PADP + ty * 4 + r];
            float4 vb4 = *(const float4*)&Vs[j * PADQ + tx * 4];
            float vb[4] = {vb4.x, vb4.y, vb4.z, vb4.w};
#pragma unroll
            for (int r = 0; r < 4; r++)
#pragma unroll
                for (int c = 0; c < 4; c++) o[r][c] += pa[r] * vb[c];
        }
        __syncthreads();
    }

    // epilogue: normalize + write ctx[b,t, h*64+d]
#pragma unroll
    for (int r = 0; r < 4; r++) {
        float inv = 1.0f / lsum[r];
        int row = q0 + ty * 4 + r;
        float4 out;
        out.x = o[r][0] * inv; out.y = o[r][1] * inv;
        out.z = o[r][2] * inv; out.w = o[r][3] * inv;
        *(float4*)&ctx[((size_t)b * Tn + row) * En + h * HDn + tx * 4] = out;
    }
}

// ---------------------------------------------------------------------------
extern "C" void kernel_launch(void* const* d_in, const int* in_sizes, int n_in,
                              void* d_out, int out_size) {
    const float*         x      = (const float*)d_in[0];
    const unsigned char* mask   = (const unsigned char*)d_in[1];
    const float*         qkv_w  = (const float*)d_in[2];
    const float*         qkv_b  = (const float*)d_in[3];
    const float*         proj_w = (const float*)d_in[4];
    const float*         proj_b = (const float*)d_in[5];
    float*               out    = (float*)d_out;

    float* qkv_s = nullptr;
    float* ctx_s = nullptr;
    cudaGetSymbolAddress((void**)&qkv_s, g_qkv);
    cudaGetSymbolAddress((void**)&ctx_s, g_ctx);

    // 1) QKV = x @ qkv_w^T + qkv_b   -> g_qkv [8192, 3072]
    {
        dim3 grid(QKVN / 128, Mn / 128);
        sgemm_tn<<<grid, 256>>>(x, qkv_w, qkv_b, qkv_s, Mn, QKVN, En);
    }

    // 2) attention -> g_ctx [8192, 1024]
    {
        cudaFuncSetAttribute(attn_kernel,
                             cudaFuncAttributeMaxDynamicSharedMemorySize,
                             ATTN_SMEM_BYTES);
        dim3 grid(Tn / 64, Bn * Hn);
        attn_kernel<<<grid, 256, ATTN_SMEM_BYTES>>>(qkv_s, mask, ctx_s);
    }

    // 3) out = ctx @ proj_w^T + proj_b
    {
        dim3 grid(En / 128, Mn / 128);
        sgemm_tn<<<grid, 256>>>(ctx_s, proj_w, proj_b, out, Mn, En, En);
    }
}

// round 4
// speedup vs baseline: 1.4832x; 1.4832x over previous
#include <cuda_runtime.h>
#include <cuda_bf16.h>
#include <stdint.h>
#include <math.h>

#define Bn   4
#define Tn   2048
#define En   1024
#define Hn   16
#define HDn  64
#define Mn   (Bn * Tn)          // 8192
#define QKVN (3 * En)           // 3072
#define GK   3072               // split K' = 3*E for bf16x3 trick

// ---------------- scratch (__device__ globals; no cudaMalloc allowed) -------
__device__ float g_qkv[(size_t)Mn * QKVN];            // 96 MB fp32
__device__ float g_ctx[(size_t)Mn * En];              // 32 MB fp32
__device__ __nv_bfloat16 g_xs [(size_t)Mn * GK];      // 48 MB  x split
__device__ __nv_bfloat16 g_ws [(size_t)QKVN * GK];    // 18 MB  qkv_w split
__device__ __nv_bfloat16 g_cs [(size_t)Mn * GK];      // 48 MB  ctx split
__device__ __nv_bfloat16 g_pws[(size_t)En * GK];      //  6 MB  proj_w split

// ---------------- helpers (sm_80/90 feature set only; NO tcgen05) ----------
__device__ __forceinline__ uint32_t smem_u32(const void* p) {
    uint32_t a;
    asm("{ .reg .u64 t; cvta.to.shared.u64 t, %1; cvt.u32.u64 %0, t; }"
        : "=r"(a) : "l"(p));
    return a;
}
__device__ __forceinline__ void cp16(uint32_t saddr, const void* g) {
    asm volatile("cp.async.cg.shared.global [%0], [%1], 16;"
                 :: "r"(saddr), "l"(g));
}
template <int N>
__device__ __forceinline__ void cp_wait() {
    asm volatile("cp.async.wait_group %0;" :: "n"(N) : "memory");
}
__device__ __forceinline__ void cp_commit() {
    asm volatile("cp.async.commit_group;" ::: "memory");
}
__device__ __forceinline__ void ldsm4(uint32_t& r0, uint32_t& r1,
                                      uint32_t& r2, uint32_t& r3,
                                      uint32_t addr) {
    asm volatile("ldmatrix.sync.aligned.m8n8.x4.shared.b16 {%0,%1,%2,%3}, [%4];"
                 : "=r"(r0), "=r"(r1), "=r"(r2), "=r"(r3) : "r"(addr));
}
__device__ __forceinline__ void mma16816(float* d, const uint32_t* a,
                                         uint32_t b0, uint32_t b1) {
    asm volatile(
        "mma.sync.aligned.m16n8k16.row.col.f32.bf16.bf16.f32 "
        "{%0,%1,%2,%3}, {%4,%5,%6,%7}, {%8,%9}, {%0,%1,%2,%3};"
        : "+f"(d[0]), "+f"(d[1]), "+f"(d[2]), "+f"(d[3])
        : "r"(a[0]), "r"(a[1]), "r"(a[2]), "r"(a[3]), "r"(b0), "r"(b1));
}
__device__ __forceinline__ uint32_t sw128(uint32_t off) {
    return off ^ ((off >> 3) & 0x70);
}

// ---------------------------------------------------------------------------
// bf16x3 split conversion: in fp32 [R, 1024] -> out bf16 [R, 3072]
// lo_sec = 1 (A-operand: [hi | lo | hi]) or 2 (B-operand: [hi | hi | lo])
// ---------------------------------------------------------------------------
struct bf16x4 { __nv_bfloat162 a, b; };

__global__ void split3_kernel(const float* __restrict__ in,
                              __nv_bfloat16* __restrict__ out, int lo_sec) {
    size_t i = ((size_t)blockIdx.x * blockDim.x + threadIdx.x) * 4;
    size_t row = i >> 10;          // K = 1024
    int col = (int)(i & 1023);
    float4 v = *(const float4*)(in + i);
    float xs[4] = {v.x, v.y, v.z, v.w};
    __nv_bfloat16 h[4], l[4];
#pragma unroll
    for (int j = 0; j < 4; j++) {
        h[j] = __float2bfloat16_rn(xs[j]);
        l[j] = __float2bfloat16_rn(xs[j] - __bfloat162float(h[j]));
    }
    bf16x4 hv, lv;
    hv.a = __nv_bfloat162(h[0], h[1]); hv.b = __nv_bfloat162(h[2], h[3]);
    lv.a = __nv_bfloat162(l[0], l[1]); lv.b = __nv_bfloat162(l[2], l[3]);
    __nv_bfloat16* o = out + row * GK;
    *(bf16x4*)(o + col) = hv;
    *(bf16x4*)(o + (3 - lo_sec) * 1024 + col) = hv;
    *(bf16x4*)(o + lo_sec * 1024 + col) = lv;
}

// ---------------------------------------------------------------------------
// HMMA bf16 GEMM: C[M,Np] = A[M,GK] @ B[Np,GK]^T + bias
// CTA 128x128, BK=64, 8 warps (4m x 2n), warp tile 32x64.
// Double-buffered cp.async; ldmatrix + mma.sync m16n8k16 (f32 accum).
// ---------------------------------------------------------------------------
#define GEMM_SMEM 65536   // A: 2 x 16KB, B: 2 x 16KB

__global__ __launch_bounds__(256, 2)
void gemm_hmma(const __nv_bfloat16* __restrict__ A,
               const __nv_bfloat16* __restrict__ B,
               const float* __restrict__ bias,
               float* __restrict__ C, int Np) {
    extern __shared__ char gsm[];
    uint32_t sb = smem_u32(gsm);
    const uint32_t SA = 0, SBB = 32768;

    int tid = threadIdx.x;
    int lane = tid & 31;
    int wid = tid >> 5;
    int wm = wid & 3;              // 0..3 -> m offset wm*32
    int wn = wid >> 2;             // 0..1 -> n offset wn*64
    int m0 = blockIdx.y * 128;
    int n0 = blockIdx.x * 128;

    // cp.async slots: 128 rows x 8 chunks of 16B per tile; 4 per thread each
    uint32_t a_soff[4]; const char* a_g[4];
    uint32_t b_soff[4]; const char* b_g[4];
#pragma unroll
    for (int i = 0; i < 4; i++) {
        int c = tid + i * 256;            // 0..1023
        int row = c >> 3, ch = c & 7;
        uint32_t off = row * 128 + ch * 16;
        a_soff[i] = sw128(off);
        b_soff[i] = sw128(off);
        a_g[i] = (const char*)(A + (size_t)(m0 + row) * GK + ch * 8);
        b_g[i] = (const char*)(B + (size_t)(n0 + row) * GK + ch * 8);
    }

    // ldmatrix lane bases
    uint32_t rA = wm * 32 + (lane & 7) + ((lane >> 3) & 1) * 8;
    uint32_t kA = ((lane >> 4) & 1) * 16;
    uint32_t rB = wn * 64 + (lane & 7) + ((lane >> 4) & 1) * 8;
    uint32_t kB = ((lane >> 3) & 1) * 16;

    float acc[2][8][4];
#pragma unroll
    for (int mt = 0; mt < 2; mt++)
#pragma unroll
        for (int t = 0; t < 8; t++)
#pragma unroll
            for (int j = 0; j < 4; j++) acc[mt][t][j] = 0.0f;

    const int NS = GK / 64;   // 48 stages

    // prologue: stages 0 and 1
#pragma unroll
    for (int s = 0; s < 2; s++) {
        uint32_t ab = sb + SA + s * 16384;
        uint32_t bb = sb + SBB + s * 16384;
        size_t goff = (size_t)s * 128;
#pragma unroll
        for (int i = 0; i < 4; i++) cp16(ab + a_soff[i], a_g[i] + goff);
#pragma unroll
        for (int i = 0; i < 4; i++) cp16(bb + b_soff[i], b_g[i] + goff);
        cp_commit();
    }

    for (int s = 0; s < NS; s++) {
        if (s == NS - 1) cp_wait<0>(); else cp_wait<1>();
        __syncthreads();

        int buf = s & 1;
        uint32_t abase = sb + SA + buf * 16384;
        uint32_t bbase = sb + SBB + buf * 16384;
#pragma unroll
        for (int kk = 0; kk < 4; kk++) {
            uint32_t a[2][4];
#pragma unroll
            for (int mt = 0; mt < 2; mt++) {
                uint32_t off = (rA + mt * 16) * 128 + kk * 32 + kA;
                ldsm4(a[mt][0], a[mt][1], a[mt][2], a[mt][3], abase + sw128(off));
            }
#pragma unroll
            for (int nt = 0; nt < 4; nt++) {
                uint32_t off = (rB + nt * 16) * 128 + kk * 32 + kB;
                uint32_t b0, b1, b2, b3;
                ldsm4(b0, b1, b2, b3, bbase + sw128(off));
                mma16816(acc[0][nt * 2 + 0], a[0], b0, b1);
                mma16816(acc[0][nt * 2 + 1], a[0], b2, b3);
                mma16816(acc[1][nt * 2 + 0], a[1], b0, b1);
                mma16816(acc[1][nt * 2 + 1], a[1], b2, b3);
            }
        }
        __syncthreads();

        if (s + 2 < NS) {
            uint32_t ab = sb + SA + buf * 16384;
            uint32_t bb = sb + SBB + buf * 16384;
            size_t goff = (size_t)(s + 2) * 128;
#pragma unroll
            for (int i = 0; i < 4; i++) cp16(ab + a_soff[i], a_g[i] + goff);
#pragma unroll
            for (int i = 0; i < 4; i++) cp16(bb + b_soff[i], b_g[i] + goff);
            cp_commit();
        }
    }

    // epilogue: d0,d1 -> (row lane/4, col (lane&3)*2); d2,d3 -> row+8
#pragma unroll
    for (int mt = 0; mt < 2; mt++) {
#pragma unroll
        for (int t = 0; t < 8; t++) {
            int row = m0 + wm * 32 + mt * 16 + (lane >> 2);
            int col = n0 + wn * 64 + t * 8 + (lane & 3) * 2;
            float2 bv = *(const float2*)(bias + col);
            float* p0 = C + (size_t)row * Np + col;
            float2 v0 = { acc[mt][t][0] + bv.x, acc[mt][t][1] + bv.y };
            *(float2*)p0 = v0;
            float* p1 = p0 + 8 * (size_t)Np;
            float2 v1 = { acc[mt][t][2] + bv.x, acc[mt][t][3] + bv.y };
            *(float2*)p1 = v1;
        }
    }
}

// ---------------------------------------------------------------------------
// Flash attention (fp32, unchanged)
// ---------------------------------------------------------------------------
#define PADQ 68
#define PADP 65
#define ATTN_SMEM_FLOATS (64 * PADQ * 3 + 64 * PADP)
#define ATTN_SMEM_BYTES  (ATTN_SMEM_FLOATS * 4)

extern __shared__ float sm_attn[];

__global__ __launch_bounds__(256)
void attn_kernel(const float* __restrict__ qkv,
                 const unsigned char* __restrict__ mask,
                 float* __restrict__ ctx) {
    float* Qs = sm_attn;
    float* Ks = Qs + 64 * PADQ;
    float* Vs = Ks + 64 * PADQ;
    float* Ps = Vs + 64 * PADQ;

    int tid = threadIdx.x;
    int tx = tid & 15;
    int ty = tid >> 4;
    int b  = blockIdx.y >> 4;
    int h  = blockIdx.y & 15;
    int q0 = blockIdx.x * 64;

    const float* base = qkv + (size_t)b * Tn * QKVN + h * HDn;
    const float  scale = 0.125f;

#pragma unroll
    for (int it = 0; it < 4; it++) {
        int idx = tid + it * 256;
        int r = idx >> 4;
        int d4 = (idx & 15) * 4;
        float4 v = *(const float4*)(base + (size_t)(q0 + r) * QKVN + d4);
        Qs[(d4 + 0) * PADQ + r] = v.x;
        Qs[(d4 + 1) * PADQ + r] = v.y;
        Qs[(d4 + 2) * PADQ + r] = v.z;
        Qs[(d4 + 3) * PADQ + r] = v.w;
    }

    float m_prev[4], lsum[4], o[4][4];
#pragma unroll
    for (int r = 0; r < 4; r++) {
        m_prev[r] = -1e30f; lsum[r] = 0.0f;
#pragma unroll
        for (int c = 0; c < 4; c++) o[r][c] = 0.0f;
    }

    const float* kbase = base + En;
    const float* vbase = base + 2 * En;

    for (int kv0 = 0; kv0 < Tn; kv0 += 64) {
#pragma unroll
        for (int it = 0; it < 4; it++) {
            int idx = tid + it * 256;
            int r = idx >> 4;
            int d4 = (idx & 15) * 4;
            float4 kv = *(const float4*)(kbase + (size_t)(kv0 + r) * QKVN + d4);
            Ks[(d4 + 0) * PADQ + r] = kv.x;
            Ks[(d4 + 1) * PADQ + r] = kv.y;
            Ks[(d4 + 2) * PADQ + r] = kv.z;
            Ks[(d4 + 3) * PADQ + r] = kv.w;
            float4 vv = *(const float4*)(vbase + (size_t)(kv0 + r) * QKVN + d4);
            *(float4*)&Vs[r * PADQ + d4] = vv;
        }
        __syncthreads();

        float s[4][4];
#pragma unroll
        for (int r = 0; r < 4; r++)
#pragma unroll
            for (int c = 0; c < 4; c++) s[r][c] = 0.0f;
#pragma unroll 16
        for (int d = 0; d < 64; d++) {
            float4 a = *(const float4*)&Qs[d * PADQ + ty * 4];
            float4 kk = *(const float4*)&Ks[d * PADQ + tx * 4];
            float ar[4] = {a.x, a.y, a.z, a.w};
            float kr[4] = {kk.x, kk.y, kk.z, kk.w};
#pragma unroll
            for (int r = 0; r < 4; r++)
#pragma unroll
                for (int c = 0; c < 4; c++) s[r][c] += ar[r] * kr[c];
        }

        int kvb = kv0 + tx * 4;
#pragma unroll
        for (int c = 0; c < 4; c++) {
            bool mk = mask[b * Tn + kvb + c] != 0;
#pragma unroll
            for (int r = 0; r < 4; r++)
                s[r][c] = mk ? -1e30f : s[r][c] * scale;
        }

        float newm[4], alpha[4], rs[4];
#pragma unroll
        for (int r = 0; r < 4; r++) {
            float mx = fmaxf(fmaxf(s[r][0], s[r][1]), fmaxf(s[r][2], s[r][3]));
#pragma unroll
            for (int off = 8; off > 0; off >>= 1)
                mx = fmaxf(mx, __shfl_xor_sync(0xffffffffu, mx, off));
            newm[r] = fmaxf(m_prev[r], mx);
            alpha[r] = __expf(m_prev[r] - newm[r]);
            float srow = 0.0f;
#pragma unroll
            for (int c = 0; c < 4; c++) {
                float p = __expf(s[r][c] - newm[r]);
                s[r][c] = p;
                srow += p;
            }
#pragma unroll
            for (int off = 8; off > 0; off >>= 1)
                srow += __shfl_xor_sync(0xffffffffu, srow, off);
            rs[r] = srow;
        }
#pragma unroll
        for (int r = 0; r < 4; r++) {
            lsum[r] = lsum[r] * alpha[r] + rs[r];
            m_prev[r] = newm[r];
#pragma unroll
            for (int c = 0; c < 4; c++) o[r][c] *= alpha[r];
        }

#pragma unroll
        for (int c = 0; c < 4; c++)
#pragma unroll
            for (int r = 0; r < 4; r++)
                Ps[(tx * 4 + c) * PADP + ty * 4 + r] = s[r][c];
        __syncthreads();

#pragma unroll 8
        for (int j = 0; j < 64; j++) {
            float pa[4];
#pragma unroll
            for (int r = 0; r < 4; r++) pa[r] = Ps[j * PADP + ty * 4 + r];
            float4 vb4 = *(const float4*)&Vs[j * PADQ + tx * 4];
            float vb[4] = {vb4.x, vb4.y, vb4.z, vb4.w};
#pragma unroll
            for (int r = 0; r < 4; r++)
#pragma unroll
                for (int c = 0; c < 4; c++) o[r][c] += pa[r] * vb[c];
        }
        __syncthreads();
    }

#pragma unroll
    for (int r = 0; r < 4; r++) {
        float inv = 1.0f / lsum[r];
        int row = q0 + ty * 4 + r;
        float4 out;
        out.x = o[r][0] * inv; out.y = o[r][1] * inv;
        out.z = o[r][2] * inv; out.w = o[r][3] * inv;
        *(float4*)&ctx[((size_t)b * Tn + row) * En + h * HDn + tx * 4] = out;
    }
}

// ---------------------------------------------------------------------------
extern "C" void kernel_launch(void* const* d_in, const int* in_sizes, int n_in,
                              void* d_out, int out_size) {
    const float*         x      = (const float*)d_in[0];
    const unsigned char* mask   = (const unsigned char*)d_in[1];
    const float*         qkv_w  = (const float*)d_in[2];
    const float*         qkv_b  = (const float*)d_in[3];
    const float*         proj_w = (const float*)d_in[4];
    const float*         proj_b = (const float*)d_in[5];
    float*               out    = (float*)d_out;

    float *qkv_s, *ctx_s;
    __nv_bfloat16 *xs, *ws, *cs, *pws;
    cudaGetSymbolAddress((void**)&qkv_s, g_qkv);
    cudaGetSymbolAddress((void**)&ctx_s, g_ctx);
    cudaGetSymbolAddress((void**)&xs,  g_xs);
    cudaGetSymbolAddress((void**)&ws,  g_ws);
    cudaGetSymbolAddress((void**)&cs,  g_cs);
    cudaGetSymbolAddress((void**)&pws, g_pws);

    cudaFuncSetAttribute(gemm_hmma,
                         cudaFuncAttributeMaxDynamicSharedMemorySize, GEMM_SMEM);
    cudaFuncSetAttribute(attn_kernel,
                         cudaFuncAttributeMaxDynamicSharedMemorySize,
                         ATTN_SMEM_BYTES);

    // 1) split x (A-operand) and qkv_w (B-operand) into bf16x3
    split3_kernel<<<(size_t)Mn * En / 4 / 256, 256>>>(x, xs, 1);
    split3_kernel<<<(size_t)QKVN * En / 4 / 256, 256>>>(qkv_w, ws, 2);

    // 2) QKV GEMM: g_qkv[8192,3072] = xs @ ws^T + qkv_b
    {
        dim3 grid(QKVN / 128, Mn / 128);
        gemm_hmma<<<grid, 256, GEMM_SMEM>>>(xs, ws, qkv_b, qkv_s, QKVN);
    }

    // 3) attention -> g_ctx
    {
        dim3 grid(Tn / 64, Bn * Hn);
        attn_kernel<<<grid, 256, ATTN_SMEM_BYTES>>>(qkv_s, mask, ctx_s);
    }

    // 4) split ctx and proj_w
    split3_kernel<<<(size_t)Mn * En / 4 / 256, 256>>>(ctx_s, cs, 1);
    split3_kernel<<<(size_t)En * En / 4 / 256, 256>>>(proj_w, pws, 2);

    // 5) proj GEMM: out = cs @ pws^T + proj_b
    {
        dim3 grid(En / 128, Mn / 128);
        gemm_hmma<<<grid, 256, GEMM_SMEM>>>(cs, pws, proj_b, out, En);
    }
}

// round 6
// speedup vs baseline: 2.9663x; 1.9999x over previous
#include <cuda_runtime.h>
#include <cuda_bf16.h>
#include <stdint.h>
#include <math.h>

#define Bn   4
#define Tn   2048
#define En   1024
#define Hn   16
#define HDn  64
#define Mn   (Bn * Tn)          // 8192
#define QKVN (3 * En)           // 3072
#define GK   3072               // split K' = 3*E for bf16x3 trick

// ---------------- scratch (__device__ globals; no cudaMalloc allowed) -------
__device__ float g_qkv[(size_t)Mn * QKVN];            // 96 MB fp32
__device__ float g_ctx[(size_t)Mn * En];              // 32 MB fp32
__device__ __nv_bfloat16 g_xs [(size_t)Mn * GK];      // 48 MB  x split
__device__ __nv_bfloat16 g_ws [(size_t)QKVN * GK];    // 18 MB  qkv_w split
__device__ __nv_bfloat16 g_cs [(size_t)Mn * GK];      // 48 MB  ctx split
__device__ __nv_bfloat16 g_pws[(size_t)En * GK];      //  6 MB  proj_w split

// ---------------- helpers (sm_80/90 feature set only) -----------------------
__device__ __forceinline__ uint32_t smem_u32(const void* p) {
    uint32_t a;
    asm("{ .reg .u64 t; cvta.to.shared.u64 t, %1; cvt.u32.u64 %0, t; }"
        : "=r"(a) : "l"(p));
    return a;
}
__device__ __forceinline__ void cp16(uint32_t saddr, const void* g) {
    asm volatile("cp.async.cg.shared.global [%0], [%1], 16;"
                 :: "r"(saddr), "l"(g));
}
template <int N>
__device__ __forceinline__ void cp_wait() {
    asm volatile("cp.async.wait_group %0;" :: "n"(N) : "memory");
}
__device__ __forceinline__ void cp_commit() {
    asm volatile("cp.async.commit_group;" ::: "memory");
}
__device__ __forceinline__ void ldsm4(uint32_t& r0, uint32_t& r1,
                                      uint32_t& r2, uint32_t& r3,
                                      uint32_t addr) {
    asm volatile("ldmatrix.sync.aligned.m8n8.x4.shared.b16 {%0,%1,%2,%3}, [%4];"
                 : "=r"(r0), "=r"(r1), "=r"(r2), "=r"(r3) : "r"(addr));
}
__device__ __forceinline__ void mma16816(float* d, const uint32_t* a,
                                         uint32_t b0, uint32_t b1) {
    asm volatile(
        "mma.sync.aligned.m16n8k16.row.col.f32.bf16.bf16.f32 "
        "{%0,%1,%2,%3}, {%4,%5,%6,%7}, {%8,%9}, {%0,%1,%2,%3};"
        : "+f"(d[0]), "+f"(d[1]), "+f"(d[2]), "+f"(d[3])
        : "r"(a[0]), "r"(a[1]), "r"(a[2]), "r"(a[3]), "r"(b0), "r"(b1));
}
__device__ __forceinline__ uint32_t sw128(uint32_t off) {
    return off ^ ((off >> 3) & 0x70);
}
// tf32 helpers
__device__ __forceinline__ uint32_t f2tf(float x) {
    uint32_t r;
    asm("cvt.rna.tf32.f32 %0, %1;" : "=r"(r) : "f"(x));
    return r;
}
__device__ __forceinline__ void mma_tf32(float* d, uint32_t a0, uint32_t a1,
                                         uint32_t a2, uint32_t a3,
                                         uint32_t b0, uint32_t b1) {
    asm volatile(
        "mma.sync.aligned.m16n8k8.row.col.f32.tf32.tf32.f32 "
        "{%0,%1,%2,%3}, {%4,%5,%6,%7}, {%8,%9}, {%0,%1,%2,%3};"
        : "+f"(d[0]), "+f"(d[1]), "+f"(d[2]), "+f"(d[3])
        : "r"(a0), "r"(a1), "r"(a2), "r"(a3), "r"(b0), "r"(b1));
}

// ---------------------------------------------------------------------------
// bf16x3 split conversion
// ---------------------------------------------------------------------------
struct bf16x4 { __nv_bfloat162 a, b; };

__global__ void split3_kernel(const float* __restrict__ in,
                              __nv_bfloat16* __restrict__ out, int lo_sec) {
    size_t i = ((size_t)blockIdx.x * blockDim.x + threadIdx.x) * 4;
    size_t row = i >> 10;          // K = 1024
    int col = (int)(i & 1023);
    float4 v = *(const float4*)(in + i);
    float xs[4] = {v.x, v.y, v.z, v.w};
    __nv_bfloat16 h[4], l[4];
#pragma unroll
    for (int j = 0; j < 4; j++) {
        h[j] = __float2bfloat16_rn(xs[j]);
        l[j] = __float2bfloat16_rn(xs[j] - __bfloat162float(h[j]));
    }
    bf16x4 hv, lv;
    hv.a = __nv_bfloat162(h[0], h[1]); hv.b = __nv_bfloat162(h[2], h[3]);
    lv.a = __nv_bfloat162(l[0], l[1]); lv.b = __nv_bfloat162(l[2], l[3]);
    __nv_bfloat16* o = out + row * GK;
    *(bf16x4*)(o + col) = hv;
    *(bf16x4*)(o + (3 - lo_sec) * 1024 + col) = hv;
    *(bf16x4*)(o + lo_sec * 1024 + col) = lv;
}

// ---------------------------------------------------------------------------
// HMMA bf16 GEMM (verified round 4)
// ---------------------------------------------------------------------------
#define GEMM_SMEM 65536

__global__ __launch_bounds__(256, 2)
void gemm_hmma(const __nv_bfloat16* __restrict__ A,
               const __nv_bfloat16* __restrict__ B,
               const float* __restrict__ bias,
               float* __restrict__ C, int Np) {
    extern __shared__ char gsm[];
    uint32_t sb = smem_u32(gsm);
    const uint32_t SA = 0, SBB = 32768;

    int tid = threadIdx.x;
    int lane = tid & 31;
    int wid = tid >> 5;
    int wm = wid & 3;
    int wn = wid >> 2;
    int m0 = blockIdx.y * 128;
    int n0 = blockIdx.x * 128;

    uint32_t a_soff[4]; const char* a_g[4];
    uint32_t b_soff[4]; const char* b_g[4];
#pragma unroll
    for (int i = 0; i < 4; i++) {
        int c = tid + i * 256;
        int row = c >> 3, ch = c & 7;
        uint32_t off = row * 128 + ch * 16;
        a_soff[i] = sw128(off);
        b_soff[i] = sw128(off);
        a_g[i] = (const char*)(A + (size_t)(m0 + row) * GK + ch * 8);
        b_g[i] = (const char*)(B + (size_t)(n0 + row) * GK + ch * 8);
    }

    uint32_t rA = wm * 32 + (lane & 7) + ((lane >> 3) & 1) * 8;
    uint32_t kA = ((lane >> 4) & 1) * 16;
    uint32_t rB = wn * 64 + (lane & 7) + ((lane >> 4) & 1) * 8;
    uint32_t kB = ((lane >> 3) & 1) * 16;

    float acc[2][8][4];
#pragma unroll
    for (int mt = 0; mt < 2; mt++)
#pragma unroll
        for (int t = 0; t < 8; t++)
#pragma unroll
            for (int j = 0; j < 4; j++) acc[mt][t][j] = 0.0f;

    const int NS = GK / 64;

#pragma unroll
    for (int s = 0; s < 2; s++) {
        uint32_t ab = sb + SA + s * 16384;
        uint32_t bb = sb + SBB + s * 16384;
        size_t goff = (size_t)s * 128;
#pragma unroll
        for (int i = 0; i < 4; i++) cp16(ab + a_soff[i], a_g[i] + goff);
#pragma unroll
        for (int i = 0; i < 4; i++) cp16(bb + b_soff[i], b_g[i] + goff);
        cp_commit();
    }

    for (int s = 0; s < NS; s++) {
        if (s == NS - 1) cp_wait<0>(); else cp_wait<1>();
        __syncthreads();

        int buf = s & 1;
        uint32_t abase = sb + SA + buf * 16384;
        uint32_t bbase = sb + SBB + buf * 16384;
#pragma unroll
        for (int kk = 0; kk < 4; kk++) {
            uint32_t a[2][4];
#pragma unroll
            for (int mt = 0; mt < 2; mt++) {
                uint32_t off = (rA + mt * 16) * 128 + kk * 32 + kA;
                ldsm4(a[mt][0], a[mt][1], a[mt][2], a[mt][3], abase + sw128(off));
            }
#pragma unroll
            for (int nt = 0; nt < 4; nt++) {
                uint32_t off = (rB + nt * 16) * 128 + kk * 32 + kB;
                uint32_t b0, b1, b2, b3;
                ldsm4(b0, b1, b2, b3, bbase + sw128(off));
                mma16816(acc[0][nt * 2 + 0], a[0], b0, b1);
                mma16816(acc[0][nt * 2 + 1], a[0], b2, b3);
                mma16816(acc[1][nt * 2 + 0], a[1], b0, b1);
                mma16816(acc[1][nt * 2 + 1], a[1], b2, b3);
            }
        }
        __syncthreads();

        if (s + 2 < NS) {
            uint32_t ab = sb + SA + buf * 16384;
            uint32_t bb = sb + SBB + buf * 16384;
            size_t goff = (size_t)(s + 2) * 128;
#pragma unroll
            for (int i = 0; i < 4; i++) cp16(ab + a_soff[i], a_g[i] + goff);
#pragma unroll
            for (int i = 0; i < 4; i++) cp16(bb + b_soff[i], b_g[i] + goff);
            cp_commit();
        }
    }

#pragma unroll
    for (int mt = 0; mt < 2; mt++) {
#pragma unroll
        for (int t = 0; t < 8; t++) {
            int row = m0 + wm * 32 + mt * 16 + (lane >> 2);
            int col = n0 + wn * 64 + t * 8 + (lane & 3) * 2;
            float2 bv = *(const float2*)(bias + col);
            float* p0 = C + (size_t)row * Np + col;
            float2 v0 = { acc[mt][t][0] + bv.x, acc[mt][t][1] + bv.y };
            *(float2*)p0 = v0;
            float* p1 = p0 + 8 * (size_t)Np;
            float2 v1 = { acc[mt][t][2] + bv.x, acc[mt][t][3] + bv.y };
            *(float2*)p1 = v1;
        }
    }
}

// ---------------------------------------------------------------------------
// Flash attention on tensor cores (tf32 HMMA m16n8k8), fp32 softmax.
// Block = 128 threads (4 warps) = one (b,h) x 64 q-rows; KV tiles of 64.
// ---------------------------------------------------------------------------
#define APAD 68
#define VPAD 72
#define ATTN2_SMEM ((64 * (3 * APAD) + 64 * VPAD + 64) * 4)   // 70912 B

__global__ __launch_bounds__(128)
void attn_tc(const float* __restrict__ qkv,
             const unsigned char* __restrict__ mask,
             float* __restrict__ ctx) {
    extern __shared__ float sm2[];
    float* Qs = sm2;                   // [64][APAD]
    float* Ks = Qs + 64 * APAD;        // [64][APAD]
    float* Ps = Ks + 64 * APAD;        // [64][APAD]
    float* Vs = Ps + 64 * APAD;        // [64][VPAD]
    float* Ms = Vs + 64 * VPAD;        // [64]

    int tid = threadIdx.x;
    int lane = tid & 31;
    int w = tid >> 5;                  // warp 0..3
    int b  = blockIdx.y >> 4;
    int h  = blockIdx.y & 15;
    int q0 = blockIdx.x * 64;

    const float* qb = qkv + (size_t)b * Tn * QKVN + h * HDn;
    const float* kb = qb + En;
    const float* vb = qb + 2 * En;

    // load Q tile (pre-scaled by 1/8 = 1/sqrt(64); exact power of two)
#pragma unroll
    for (int it = 0; it < 8; it++) {
        int idx = tid + it * 128;      // 0..1023
        int r = idx >> 4;
        int c4 = (idx & 15) * 4;
        float4 v = *(const float4*)(qb + (size_t)(q0 + r) * QKVN + c4);
        v.x *= 0.125f; v.y *= 0.125f; v.z *= 0.125f; v.w *= 0.125f;
        *(float4*)&Qs[r * APAD + c4] = v;
    }

    int r0 = lane >> 2;                // 0..7
    int cq = lane & 3;                 // quad col

    float oacc[8][4];
#pragma unroll
    for (int n = 0; n < 8; n++)
#pragma unroll
        for (int j = 0; j < 4; j++) oacc[n][j] = 0.0f;
    float m0f = -1e30f, m1f = -1e30f, l0 = 0.0f, l1 = 0.0f;

    for (int kv0 = 0; kv0 < Tn; kv0 += 64) {
        // load K, V tiles + mask
#pragma unroll
        for (int it = 0; it < 8; it++) {
            int idx = tid + it * 128;
            int r = idx >> 4;
            int c4 = (idx & 15) * 4;
            float4 kv = *(const float4*)(kb + (size_t)(kv0 + r) * QKVN + c4);
            *(float4*)&Ks[r * APAD + c4] = kv;
            float4 vv = *(const float4*)(vb + (size_t)(kv0 + r) * QKVN + c4);
            *(float4*)&Vs[r * VPAD + c4] = vv;
        }
        if (tid < 64)
            Ms[tid] = mask[b * Tn + kv0 + tid] ? -1e30f : 0.0f;
        __syncthreads();

        // ---- S = Q K^T  (tf32 mma) ----
        float sacc[8][4];
#pragma unroll
        for (int n = 0; n < 8; n++)
#pragma unroll
            for (int j = 0; j < 4; j++) sacc[n][j] = 0.0f;

#pragma unroll
        for (int k = 0; k < 8; k++) {
            int kc = k * 8 + cq;
            uint32_t a0 = f2tf(Qs[(w * 16 + r0) * APAD + kc]);
            uint32_t a1 = f2tf(Qs[(w * 16 + r0 + 8) * APAD + kc]);
            uint32_t a2 = f2tf(Qs[(w * 16 + r0) * APAD + kc + 4]);
            uint32_t a3 = f2tf(Qs[(w * 16 + r0 + 8) * APAD + kc + 4]);
#pragma unroll
            for (int n = 0; n < 8; n++) {
                int krow = n * 8 + r0;          // kv index (B col)
                uint32_t b0 = f2tf(Ks[krow * APAD + kc]);
                uint32_t b1 = f2tf(Ks[krow * APAD + kc + 4]);
                mma_tf32(sacc[n], a0, a1, a2, a3, b0, b1);
            }
        }

        // ---- mask + online softmax (fp32) ----
        float mx0 = -1e30f, mx1 = -1e30f;
#pragma unroll
        for (int n = 0; n < 8; n++) {
            int c = n * 8 + cq * 2;
            float ma = Ms[c], mb2 = Ms[c + 1];
            sacc[n][0] += ma; sacc[n][1] += mb2;
            sacc[n][2] += ma; sacc[n][3] += mb2;
            mx0 = fmaxf(mx0, fmaxf(sacc[n][0], sacc[n][1]));
            mx1 = fmaxf(mx1, fmaxf(sacc[n][2], sacc[n][3]));
        }
        mx0 = fmaxf(mx0, __shfl_xor_sync(0xffffffffu, mx0, 1));
        mx0 = fmaxf(mx0, __shfl_xor_sync(0xffffffffu, mx0, 2));
        mx1 = fmaxf(mx1, __shfl_xor_sync(0xffffffffu, mx1, 1));
        mx1 = fmaxf(mx1, __shfl_xor_sync(0xffffffffu, mx1, 2));

        float nm0 = fmaxf(m0f, mx0), nm1 = fmaxf(m1f, mx1);
        float al0 = __expf(m0f - nm0), al1 = __expf(m1f - nm1);
        float rs0 = 0.0f, rs1 = 0.0f;
#pragma unroll
        for (int n = 0; n < 8; n++) {
            sacc[n][0] = __expf(sacc[n][0] - nm0);
            sacc[n][1] = __expf(sacc[n][1] - nm0);
            sacc[n][2] = __expf(sacc[n][2] - nm1);
            sacc[n][3] = __expf(sacc[n][3] - nm1);
            rs0 += sacc[n][0] + sacc[n][1];
            rs1 += sacc[n][2] + sacc[n][3];
        }
        rs0 += __shfl_xor_sync(0xffffffffu, rs0, 1);
        rs0 += __shfl_xor_sync(0xffffffffu, rs0, 2);
        rs1 += __shfl_xor_sync(0xffffffffu, rs1, 1);
        rs1 += __shfl_xor_sync(0xffffffffu, rs1, 2);

        l0 = l0 * al0 + rs0;  m0f = nm0;
        l1 = l1 * al1 + rs1;  m1f = nm1;
#pragma unroll
        for (int n = 0; n < 8; n++) {
            oacc[n][0] *= al0; oacc[n][1] *= al0;
            oacc[n][2] *= al1; oacc[n][3] *= al1;
        }

        // ---- store P to smem (warp-private rows) ----
#pragma unroll
        for (int n = 0; n < 8; n++) {
            int c = n * 8 + cq * 2;
            *(float2*)&Ps[(w * 16 + r0) * APAD + c] =
                make_float2(sacc[n][0], sacc[n][1]);
            *(float2*)&Ps[(w * 16 + r0 + 8) * APAD + c] =
                make_float2(sacc[n][2], sacc[n][3]);
        }
        __syncwarp();

        // ---- O += P V  (tf32 mma; k = kv dim, n = head dim) ----
#pragma unroll
        for (int k = 0; k < 8; k++) {
            int kc = k * 8 + cq;
            uint32_t a0 = f2tf(Ps[(w * 16 + r0) * APAD + kc]);
            uint32_t a1 = f2tf(Ps[(w * 16 + r0 + 8) * APAD + kc]);
            uint32_t a2 = f2tf(Ps[(w * 16 + r0) * APAD + kc + 4]);
            uint32_t a3 = f2tf(Ps[(w * 16 + r0 + 8) * APAD + kc + 4]);
#pragma unroll
            for (int n = 0; n < 8; n++) {
                int dcol = n * 8 + r0;          // head-dim col
                uint32_t b0 = f2tf(Vs[(k * 8 + cq) * VPAD + dcol]);
                uint32_t b1 = f2tf(Vs[(k * 8 + cq + 4) * VPAD + dcol]);
                mma_tf32(oacc[n], a0, a1, a2, a3, b0, b1);
            }
        }
        __syncthreads();
    }

    // epilogue
    float inv0 = 1.0f / l0, inv1 = 1.0f / l1;
    int row0 = q0 + w * 16 + r0;
#pragma unroll
    for (int n = 0; n < 8; n++) {
        int col = h * HDn + n * 8 + cq * 2;
        float* p0 = &ctx[((size_t)b * Tn + row0) * En + col];
        *(float2*)p0 = make_float2(oacc[n][0] * inv0, oacc[n][1] * inv0);
        float* p1 = &ctx[((size_t)b * Tn + row0 + 8) * En + col];
        *(float2*)p1 = make_float2(oacc[n][2] * inv1, oacc[n][3] * inv1);
    }
}

// ---------------------------------------------------------------------------
extern "C" void kernel_launch(void* const* d_in, const int* in_sizes, int n_in,
                              void* d_out, int out_size) {
    const float*         x      = (const float*)d_in[0];
    const unsigned char* mask   = (const unsigned char*)d_in[1];
    const float*         qkv_w  = (const float*)d_in[2];
    const float*         qkv_b  = (const float*)d_in[3];
    const float*         proj_w = (const float*)d_in[4];
    const float*         proj_b = (const float*)d_in[5];
    float*               out    = (float*)d_out;

    float *qkv_s, *ctx_s;
    __nv_bfloat16 *xs, *ws, *cs, *pws;
    cudaGetSymbolAddress((void**)&qkv_s, g_qkv);
    cudaGetSymbolAddress((void**)&ctx_s, g_ctx);
    cudaGetSymbolAddress((void**)&xs,  g_xs);
    cudaGetSymbolAddress((void**)&ws,  g_ws);
    cudaGetSymbolAddress((void**)&cs,  g_cs);
    cudaGetSymbolAddress((void**)&pws, g_pws);

    cudaFuncSetAttribute(gemm_hmma,
                         cudaFuncAttributeMaxDynamicSharedMemorySize, GEMM_SMEM);
    cudaFuncSetAttribute(attn_tc,
                         cudaFuncAttributeMaxDynamicSharedMemorySize, ATTN2_SMEM);

    // 1) split x and qkv_w into bf16x3
    split3_kernel<<<(size_t)Mn * En / 4 / 256, 256>>>(x, xs, 1);
    split3_kernel<<<(size_t)QKVN * En / 4 / 256, 256>>>(qkv_w, ws, 2);

    // 2) QKV GEMM
    {
        dim3 grid(QKVN / 128, Mn / 128);
        gemm_hmma<<<grid, 256, GEMM_SMEM>>>(xs, ws, qkv_b, qkv_s, QKVN);
    }

    // 3) attention (tf32 tensor cores)
    {
        dim3 grid(Tn / 64, Bn * Hn);
        attn_tc<<<grid, 128, ATTN2_SMEM>>>(qkv_s, mask, ctx_s);
    }

    // 4) split ctx and proj_w
    split3_kernel<<<(size_t)Mn * En / 4 / 256, 256>>>(ctx_s, cs, 1);
    split3_kernel<<<(size_t)En * En / 4 / 256, 256>>>(proj_w, pws, 2);

    // 5) proj GEMM
    {
        dim3 grid(En / 128, Mn / 128);
        gemm_hmma<<<grid, 256, GEMM_SMEM>>>(cs, pws, proj_b, out, En);
    }
}